// round 7
// baseline (speedup 1.0000x reference)
#include <cuda_runtime.h>
#include <stdint.h>

#define BATCH   16
#define NANCH   25200
#define NCLS    80
#define STRIDE  85
#define MAXC    1000
#define CONF_T  0.25f
#define IOU_T   0.45f
#define BINS    4096
#define CAP     1088    // contiguous candidate buffer (cnt <= 999 + hist[T])
#define SLOTCAP 64      // max entries per (batch,bin) bucket (avg ~5, Poisson tail << 64)
#define SAPB    128     // anchors per block in k_score

// ---------------- scratch (no allocations allowed) ----------------
__device__ __align__(16) unsigned int g_hist[BATCH * BINS];   // zero-init; re-zeroed each run
__device__ unsigned long long g_bkey[BATCH * BINS * SLOTCAP]; // per-bin key buckets
__device__ float4             g_bbox[BATCH * BINS * SLOTCAP]; // per-bin raw xywh

// raw output-box data per rank, [BATCH][MAXC]
__device__ float g_bx1[BATCH * MAXC], g_by1[BATCH * MAXC];
__device__ float g_bx2[BATCH * MAXC], g_by2[BATCH * MAXC];
__device__ float g_conf[BATCH * MAXC];

// ---------------- K1: thread-per-anchor score/argmax -> global bin buckets ----
__global__ void __launch_bounds__(SAPB) k_score(const float* __restrict__ pred)
{
    __shared__ __align__(16) float s[SAPB * STRIDE];   // 43520 B

    int tid = threadIdx.x;
    int ga0 = blockIdx.x * SAPB;

    // coalesced float4 staging, fully unrolled (MLP = 21 per thread)
    const float4* src = (const float4*)(pred + (size_t)ga0 * STRIDE);
    float4*       dst = (float4*)s;
#pragma unroll
    for (int k = 0; k < 21; ++k)
        dst[tid + k * SAPB] = __ldg(src + tid + k * SAPB);
    if (tid < (SAPB * STRIDE) / 4 - 21 * SAPB)         // 2720 - 2688 = 32
        dst[tid + 21 * SAPB] = __ldg(src + tid + 21 * SAPB);
    __syncthreads();

    // one anchor per thread; stride-85 rows are bank-conflict-free (gcd(21,32)=1)
    int base = tid * STRIDE;
    float obj = s[base + 4];
    if (obj > CONF_T) {
        float bv = -1.0f; int bc = 0;
#pragma unroll 16
        for (int ci = 0; ci < NCLS; ++ci) {
            float p = __fmul_rn(s[base + 5 + ci], obj);   // first-argmax (strict >)
            if (p > bv) { bv = p; bc = ci; }
        }
        if (bv > CONF_T) {
            unsigned bits = __float_as_uint(bv);
            // score in (0.25,1): bits in (0x3E800000,0x3F800000) -> 4096 exact bins
            int bin = (int)(bits >> 12) - 0x3E800;
            bin = bin < 0 ? 0 : (bin > BINS - 1 ? BINS - 1 : bin);

            int ga = ga0 + tid;
            int b  = ga / NANCH;
            int n  = ga - b * NANCH;

            unsigned slot = atomicAdd(&g_hist[b * BINS + bin], 1u);
            if (slot < SLOTCAP) {
                size_t sl = (size_t)(b * BINS + bin) * SLOTCAP + slot;
                // key = score_bits:32 | (0x7FFF-idx):15 | cls:8 (idx unique -> cls inert)
                g_bkey[sl] = ((unsigned long long)bits << 32)
                           | ((unsigned long long)(0x7FFFu - (unsigned)n) << 8)
                           | (unsigned long long)(unsigned)bc;
                g_bbox[sl] = make_float4(s[base + 0], s[base + 1],
                                         s[base + 2], s[base + 3]);
            }
        }
    }
}

// ---------------- K2 (fused): top-1000 via bin suffix sums + NMS ------------
__global__ void __launch_bounds__(1024) k_fused(float* __restrict__ out)
{
    int b    = blockIdx.x;
    int t    = threadIdx.x;
    int wrp  = t >> 5;
    int lane = t & 31;

    __shared__ unsigned short     sSufB[BINS];        // 8192 B: cnt in bins >= bin
    __shared__ unsigned long long sKeys[CAP];         // 8704 B
    __shared__ float sNx1[MAXC], sNy1[MAXC], sNx2[MAXC], sNy2[MAXC], sNa[MAXC]; // 20000 B
    __shared__ unsigned int       sMask[NCLS * 32];   // 10240 B: per-class rank bitmasks
    __shared__ unsigned int       sFill[32];          // filled-rank bitmask
    __shared__ unsigned int       sWarp[32];
    __shared__ int sT;

    // ---- A: vector load 4 bins, zero global hist (graph-replay invariant) ----
    uint4 hv = *(const uint4*)&g_hist[b * BINS + 4 * t];
    *(uint4*)&g_hist[b * BINS + 4 * t] = make_uint4(0u, 0u, 0u, 0u);

    if (t == 0) sT = BINS;
    if (t < 32) sFill[t] = 0u;
    for (int i = t; i < NCLS * 32; i += 1024) sMask[i] = 0u;

    // ---- B: suffix sums via shuffle scan ----
    unsigned int csum = hv.x + hv.y + hv.z + hv.w;
    unsigned int v = csum;                            // inclusive suffix within warp
#pragma unroll
    for (int off = 1; off < 32; off <<= 1) {
        unsigned int u = __shfl_down_sync(0xffffffffu, v, off);
        if (lane + off < 32) v += u;
    }
    if (lane == 0) sWarp[wrp] = v;
    __syncthreads();
    if (wrp == 0) {
        unsigned int w = sWarp[lane];
        unsigned int ws = w;
#pragma unroll
        for (int off = 1; off < 32; off <<= 1) {
            unsigned int u = __shfl_down_sync(0xffffffffu, ws, off);
            if (lane + off < 32) ws += u;
        }
        sWarp[lane] = ws - w;                         // exclusive (warps above)
    }
    __syncthreads();
    {
        unsigned int chunkSuf = v + sWarp[wrp];       // count in bins >= 4t
        sSufB[4 * t + 0] = (unsigned short)chunkSuf;
        sSufB[4 * t + 1] = (unsigned short)(chunkSuf - hv.x);
        sSufB[4 * t + 2] = (unsigned short)(chunkSuf - hv.x - hv.y);
        sSufB[4 * t + 3] = (unsigned short)(chunkSuf - hv.x - hv.y - hv.z);
    }
    __syncthreads();

    // ---- C: threshold bin T (parallel over bins) ----
    unsigned int total = sSufB[0];
    unsigned int K = total < MAXC ? total : MAXC;
    if (K > 0) {
#pragma unroll
        for (int k = 0; k < 4; ++k) {
            int bi = 4 * t + k;
            unsigned int hi = sSufB[bi];
            unsigned int lo = (bi + 1 < BINS) ? sSufB[bi + 1] : 0u;
            if (hi >= K && lo < K) sT = bi;           // unique writer
        }
    }
    __syncthreads();

    int T   = sT;
    int cnt = (T < BINS) ? (int)sSufB[T] : 0;
    if (cnt > CAP) cnt = CAP;

    // ---- D: warp-per-bin parallel bucket copy into contiguous keys ----
    for (int bin = T + wrp; bin < BINS; bin += 32) {
        unsigned int off = (bin + 1 < BINS) ? sSufB[bin + 1] : 0u;
        int cb = (int)sSufB[bin] - (int)off;
        if (cb > SLOTCAP) cb = SLOTCAP;
        if (lane < cb && (int)off + lane < CAP)
            sKeys[off + lane] =
                __ldg(&g_bkey[(size_t)(b * BINS + bin) * SLOTCAP + lane]);
    }
    __syncthreads();

    // ---- E: O(bucket) exact ranking + candidate prep (box from g_bbox) ----
    for (int pos = t; pos < cnt; pos += 1024) {
        unsigned long long mykey = sKeys[pos];
        unsigned bits = (unsigned)(mykey >> 32);
        int bin = (int)(bits >> 12) - 0x3E800;
        bin = bin < 0 ? 0 : (bin > BINS - 1 ? BINS - 1 : bin);

        unsigned int off = (bin + 1 < BINS) ? sSufB[bin + 1] : 0u;
        int hi = (int)sSufB[bin]; if (hi > CAP) hi = CAP;

        int rank = (int)off;
        for (int i = (int)off; i < hi; ++i)
            rank += (sKeys[i] > mykey) ? 1 : 0;

        if (rank < MAXC) {
            int   cls  = (int)(mykey & 0xFF);
            int   slot = pos - (int)off;
            float4 bx = __ldg(&g_bbox[(size_t)(b * BINS + bin) * SLOTCAP + slot]);

            float hw = __fmul_rn(bx.z, 0.5f), hh = __fmul_rn(bx.w, 0.5f);
            float bx1 = __fsub_rn(bx.x, hw), by1 = __fsub_rn(bx.y, hh);
            float bx2 = __fadd_rn(bx.x, hw), by2 = __fadd_rn(bx.y, hh);
            float offc = __fmul_rn((float)cls, 4096.0f);   // exact (pow2)
            float ox1 = __fadd_rn(bx1, offc), oy1 = __fadd_rn(by1, offc);
            float ox2 = __fadd_rn(bx2, offc), oy2 = __fadd_rn(by2, offc);
            float area = __fmul_rn(__fsub_rn(ox2, ox1), __fsub_rn(oy2, oy1));

            sNx1[rank] = ox1; sNy1[rank] = oy1;
            sNx2[rank] = ox2; sNy2[rank] = oy2;
            sNa[rank]  = area;
            atomicOr(&sMask[cls * 32 + (rank >> 5)], 1u << (rank & 31));
            atomicOr(&sFill[rank >> 5], 1u << (rank & 31));

            int o = b * MAXC + rank;
            g_bx1[o] = bx1; g_by1[o] = by1; g_bx2[o] = bx2; g_by2[o] = by2;
            g_conf[o] = __uint_as_float(bits);
        }
    }
    __syncthreads();

    // ---- F: zero rows for empty ranks (disjoint from G's rows) ----
    for (int r = t; r < MAXC; r += 1024) {
        if (!((sFill[r >> 5] >> (r & 31)) & 1u)) {
            int o = b * MAXC + r;
            float2* row = (float2*)(out + (size_t)o * 6);
            row[0] = make_float2(0.f, 0.f);
            row[1] = make_float2(0.f, 0.f);
            row[2] = make_float2(0.f, 0.f);
            out[(size_t)BATCH * MAXC * 6 + o] = 0.f;
        }
    }

    // ---- G: per-class greedy NMS via rank bitmasks, one warp per class ----
    // Cross-class IoU is exactly 0 (class offsets are multiples of 4096,
    // raw boxes in [-0.5,1.5]) -> reference greedy loop decomposes by class.
    for (int c = wrp; c < NCLS; c += 32) {
        unsigned word = sMask[c * 32 + lane];         // lane l holds ranks [32l,32l+32)
        unsigned ne   = __ballot_sync(0xffffffffu, word != 0u);

        int   nk = 0;
        float kx1 = 0, ky1 = 0, kx2 = 0, ky2 = 0, ka = 0;

        while (ne) {                                   // ascending word index = rank order
            int w = __ffs(ne) - 1;
            ne &= ne - 1;
            unsigned m = __shfl_sync(0xffffffffu, word, w);

            while (m) {
                int li = __ffs(m) - 1;
                m &= m - 1;
                int ri = w * 32 + li;

                float qx1 = sNx1[ri], qy1 = sNy1[ri];
                float qx2 = sNx2[ri], qy2 = sNy2[ri], qa = sNa[ri];

                int sup = 0;
                if (lane < nk) {
                    float ltx = fmaxf(kx1, qx1);
                    float lty = fmaxf(ky1, qy1);
                    float rbx = fminf(kx2, qx2);
                    float rby = fminf(ky2, qy2);
                    float ww  = fmaxf(__fsub_rn(rbx, ltx), 0.0f);
                    float hh  = fmaxf(__fsub_rn(rby, lty), 0.0f);
                    float inter = __fmul_rn(ww, hh);
                    float den = __fadd_rn(__fsub_rn(__fadd_rn(ka, qa), inter), 1e-7f);
                    sup = (__fdiv_rn(inter, den) > IOU_T) ? 1 : 0;
                }
                unsigned sb = __ballot_sync(0xffffffffu, sup);

                int o = b * MAXC + ri;
                float2* row = (float2*)(out + (size_t)o * 6);
                if (!sb) {
                    if (lane == nk) { kx1 = qx1; ky1 = qy1; kx2 = qx2; ky2 = qy2; ka = qa; }
                    nk++;
                    if (lane == 0) {
                        row[0] = make_float2(g_bx1[o], g_by1[o]);
                        row[1] = make_float2(g_bx2[o], g_conf[o]);
                        row[2] = make_float2(0.f, 0.f);           // placeholder
                        // fix layout: write full row scalar-wise instead
                    }
                } else {
                    if (lane == 0) {
                        row[0] = make_float2(0.f, 0.f);
                        row[1] = make_float2(0.f, 0.f);
                        row[2] = make_float2(0.f, 0.f);
                        out[(size_t)BATCH * MAXC * 6 + o] = 0.f;
                    }
                }
                if (!sb && lane == 0) {
                    float* rs = out + (size_t)o * 6;
                    rs[0] = g_bx1[o]; rs[1] = g_by1[o];
                    rs[2] = g_bx2[o]; rs[3] = g_by2[o];
                    rs[4] = g_conf[o];
                    rs[5] = (float)c;
                    out[(size_t)BATCH * MAXC * 6 + o] = 1.0f;
                }
            }
        }
    }
}

// ---------------- launch ----------------
extern "C" void kernel_launch(void* const* d_in, const int* in_sizes, int n_in,
                              void* d_out, int out_size)
{
    (void)in_sizes; (void)n_in; (void)out_size;
    const float* pred = (const float*)d_in[0];
    float* out = (float*)d_out;

    k_score<<<(BATCH * NANCH) / SAPB, SAPB>>>(pred);   // 3150 blocks
    k_fused<<<BATCH, 1024>>>(out);
}

// round 8
// speedup vs baseline: 1.2152x; 1.2152x over previous
#include <cuda_runtime.h>
#include <stdint.h>

#define BATCH   16
#define NANCH   25200
#define NCLS    80
#define STRIDE  85
#define MAXC    1000
#define CONF_T  0.25f
#define IOU_T   0.45f
#define BINS    4096
#define SLOTCAP 64      // max entries per (batch,bin) bucket
#define SAPB    128     // anchors per block in k_score
#define CPB     8       // classes per block in k_nms

// ---------------- scratch (no allocations allowed) ----------------
__device__ __align__(16) unsigned int g_hist[BATCH * BINS];   // zero-init; re-zeroed each run
__device__ unsigned long long g_bkey[BATCH * BINS * SLOTCAP]; // per-bin key buckets
__device__ float4             g_bbox[BATCH * BINS * SLOTCAP]; // per-bin raw xywh

// per-rank candidate data, [BATCH][MAXC]
__device__ float g_nx1[BATCH * MAXC], g_ny1[BATCH * MAXC];    // offset boxes
__device__ float g_nx2[BATCH * MAXC], g_ny2[BATCH * MAXC];
__device__ float g_na [BATCH * MAXC];                         // offset areas
__device__ float g_bx1[BATCH * MAXC], g_by1[BATCH * MAXC];    // raw boxes
__device__ float g_bx2[BATCH * MAXC], g_by2[BATCH * MAXC];
__device__ float g_conf[BATCH * MAXC];
__device__ unsigned int g_mask[BATCH * NCLS * 32];            // per-class rank bitmasks

// ---------------- K1: thread-per-anchor score/argmax -> global bin buckets ----
__global__ void __launch_bounds__(SAPB) k_score(const float* __restrict__ pred)
{
    __shared__ __align__(16) float s[SAPB * STRIDE];   // 43520 B

    int tid = threadIdx.x;
    int ga0 = blockIdx.x * SAPB;

    // coalesced float4 staging, fully unrolled (MLP = 21 per thread)
    const float4* src = (const float4*)(pred + (size_t)ga0 * STRIDE);
    float4*       dst = (float4*)s;
#pragma unroll
    for (int k = 0; k < 21; ++k)
        dst[tid + k * SAPB] = __ldg(src + tid + k * SAPB);
    if (tid < (SAPB * STRIDE) / 4 - 21 * SAPB)         // 2720 - 2688 = 32
        dst[tid + 21 * SAPB] = __ldg(src + tid + 21 * SAPB);
    __syncthreads();

    // one anchor per thread; stride-85 rows are bank-conflict-free (gcd(21,32)=1)
    int base = tid * STRIDE;
    float obj = s[base + 4];
    if (obj > CONF_T) {
        float bv = -1.0f; int bc = 0;
#pragma unroll 16
        for (int ci = 0; ci < NCLS; ++ci) {
            float p = __fmul_rn(s[base + 5 + ci], obj);   // first-argmax (strict >)
            if (p > bv) { bv = p; bc = ci; }
        }
        if (bv > CONF_T) {
            unsigned bits = __float_as_uint(bv);
            // score in (0.25,1): bits in (0x3E800000,0x3F800000) -> 4096 exact bins
            int bin = (int)(bits >> 12) - 0x3E800;
            bin = bin < 0 ? 0 : (bin > BINS - 1 ? BINS - 1 : bin);

            int ga = ga0 + tid;
            int b  = ga / NANCH;
            int n  = ga - b * NANCH;

            unsigned slot = atomicAdd(&g_hist[b * BINS + bin], 1u);
            if (slot < SLOTCAP) {
                size_t sl = (size_t)(b * BINS + bin) * SLOTCAP + slot;
                // key = score_bits:32 | (0x7FFF-idx):15 | cls:8 (idx unique -> cls inert)
                g_bkey[sl] = ((unsigned long long)bits << 32)
                           | ((unsigned long long)(0x7FFFu - (unsigned)n) << 8)
                           | (unsigned long long)(unsigned)bc;
                g_bbox[sl] = make_float4(s[base + 0], s[base + 1],
                                         s[base + 2], s[base + 3]);
            }
        }
    }
}

// helper: per-lane candidate finalize (rank -> global arrays + masks)
__device__ __forceinline__ void emit_candidate(
    int b, unsigned long long key, int rank, size_t slot,
    unsigned int* sMask, unsigned int* sFill)
{
    if (rank >= MAXC) return;
    unsigned bits = (unsigned)(key >> 32);
    int      cls  = (int)(key & 0xFF);
    float4   bx   = __ldg(&g_bbox[slot]);

    float hw = __fmul_rn(bx.z, 0.5f), hh = __fmul_rn(bx.w, 0.5f);
    float bx1 = __fsub_rn(bx.x, hw), by1 = __fsub_rn(bx.y, hh);
    float bx2 = __fadd_rn(bx.x, hw), by2 = __fadd_rn(bx.y, hh);
    float offc = __fmul_rn((float)cls, 4096.0f);      // exact (pow2)
    float ox1 = __fadd_rn(bx1, offc), oy1 = __fadd_rn(by1, offc);
    float ox2 = __fadd_rn(bx2, offc), oy2 = __fadd_rn(by2, offc);
    float area = __fmul_rn(__fsub_rn(ox2, ox1), __fsub_rn(oy2, oy1));

    int o = b * MAXC + rank;
    g_nx1[o] = ox1; g_ny1[o] = oy1; g_nx2[o] = ox2; g_ny2[o] = oy2;
    g_na[o]  = area;
    g_bx1[o] = bx1; g_by1[o] = by1; g_bx2[o] = bx2; g_by2[o] = by2;
    g_conf[o] = __uint_as_float(bits);
    atomicOr(&sMask[cls * 32 + (rank >> 5)], 1u << (rank & 31));
    atomicOr(&sFill[rank >> 5], 1u << (rank & 31));
}

// ---------------- K2: prep — suffix sums, threshold, register ranking -------
__global__ void __launch_bounds__(1024) k_prep(float* __restrict__ out)
{
    int b    = blockIdx.x;
    int t    = threadIdx.x;
    int wrp  = t >> 5;
    int lane = t & 31;

    __shared__ unsigned short sSufB[BINS];        // count of candidates in bins >= bin
    __shared__ unsigned int   sMask[NCLS * 32];   // per-class rank bitmasks
    __shared__ unsigned int   sFill[32];
    __shared__ unsigned int   sWarp[32];
    __shared__ int sT;

    // ---- A: vector load 4 bins, zero global hist (graph-replay invariant) ----
    uint4 hv = *(const uint4*)&g_hist[b * BINS + 4 * t];
    *(uint4*)&g_hist[b * BINS + 4 * t] = make_uint4(0u, 0u, 0u, 0u);

    if (t == 0) sT = BINS;
    if (t < 32) sFill[t] = 0u;
    for (int i = t; i < NCLS * 32; i += 1024) sMask[i] = 0u;

    // ---- B: suffix sums via shuffle scan ----
    unsigned int csum = hv.x + hv.y + hv.z + hv.w;
    unsigned int v = csum;
#pragma unroll
    for (int off = 1; off < 32; off <<= 1) {
        unsigned int u = __shfl_down_sync(0xffffffffu, v, off);
        if (lane + off < 32) v += u;
    }
    if (lane == 0) sWarp[wrp] = v;
    __syncthreads();
    if (wrp == 0) {
        unsigned int w = sWarp[lane];
        unsigned int ws = w;
#pragma unroll
        for (int off = 1; off < 32; off <<= 1) {
            unsigned int u = __shfl_down_sync(0xffffffffu, ws, off);
            if (lane + off < 32) ws += u;
        }
        sWarp[lane] = ws - w;                     // exclusive (warps above)
    }
    __syncthreads();
    {
        unsigned int chunkSuf = v + sWarp[wrp];   // count in bins >= 4t
        sSufB[4 * t + 0] = (unsigned short)chunkSuf;
        sSufB[4 * t + 1] = (unsigned short)(chunkSuf - hv.x);
        sSufB[4 * t + 2] = (unsigned short)(chunkSuf - hv.x - hv.y);
        sSufB[4 * t + 3] = (unsigned short)(chunkSuf - hv.x - hv.y - hv.z);
    }
    __syncthreads();

    // ---- C: threshold bin T (parallel over bins) ----
    unsigned int total = sSufB[0];
    unsigned int K = total < MAXC ? total : MAXC;
    if (K > 0) {
#pragma unroll
        for (int k = 0; k < 4; ++k) {
            int bi = 4 * t + k;
            unsigned int hi = sSufB[bi];
            unsigned int lo = (bi + 1 < BINS) ? sSufB[bi + 1] : 0u;
            if (hi >= K && lo < K) sT = bi;       // unique writer
        }
    }
    __syncthreads();
    int T = sT;

    // ---- DE: warp-per-bin register ranking + candidate emit ----
    for (int bin = T + wrp; bin < BINS; bin += 32) {
        unsigned int off = (bin + 1 < BINS) ? sSufB[bin + 1] : 0u;
        int cb = (int)sSufB[bin] - (int)off;
        if (cb <= 0) continue;
        if (cb > SLOTCAP) cb = SLOTCAP;

        size_t sb = (size_t)(b * BINS + bin) * SLOTCAP;
        unsigned long long k1 = (lane < cb)      ? __ldg(&g_bkey[sb + lane])      : 0ull;
        unsigned long long k2 = (32 + lane < cb) ? __ldg(&g_bkey[sb + 32 + lane]) : 0ull;

        int n1 = cb < 32 ? cb : 32;
        int n2 = cb - n1;
        int r1 = 0, r2 = 0;
        for (int j = 0; j < n1; ++j) {
            unsigned long long kj = __shfl_sync(0xffffffffu, k1, j);
            r1 += (kj > k1) ? 1 : 0;
            r2 += (kj > k2) ? 1 : 0;
        }
        for (int j = 0; j < n2; ++j) {
            unsigned long long kj = __shfl_sync(0xffffffffu, k2, j);
            r1 += (kj > k1) ? 1 : 0;
            r2 += (kj > k2) ? 1 : 0;
        }

        if (lane < cb)      emit_candidate(b, k1, (int)off + r1, sb + lane,      sMask, sFill);
        if (32 + lane < cb) emit_candidate(b, k2, (int)off + r2, sb + 32 + lane, sMask, sFill);
    }
    __syncthreads();

    // ---- F: copy masks to global; zero rows for empty ranks ----
    for (int i = t; i < NCLS * 32; i += 1024)
        g_mask[b * NCLS * 32 + i] = sMask[i];

    for (int r = t; r < MAXC; r += 1024) {
        if (!((sFill[r >> 5] >> (r & 31)) & 1u)) {
            int o = b * MAXC + r;
            float2* row = (float2*)(out + (size_t)o * 6);
            row[0] = make_float2(0.f, 0.f);
            row[1] = make_float2(0.f, 0.f);
            row[2] = make_float2(0.f, 0.f);
            out[(size_t)BATCH * MAXC * 6 + o] = 0.f;
        }
    }
}

// ---------------- K3: per-(batch,class) greedy NMS, warp per class ----------
// Cross-class IoU is exactly 0 (class offsets are multiples of 4096, raw boxes
// in [-0.5,1.5]) -> reference greedy loop decomposes by class.
__global__ void __launch_bounds__(CPB * 32) k_nms(float* __restrict__ out)
{
    const int BLOCKS_PER_B = NCLS / CPB;              // 10
    int b    = blockIdx.x / BLOCKS_PER_B;
    int wrp  = threadIdx.x >> 5;
    int lane = threadIdx.x & 31;
    int c    = (blockIdx.x % BLOCKS_PER_B) * CPB + wrp;

    unsigned word = __ldg(&g_mask[(b * NCLS + c) * 32 + lane]);
    unsigned ne   = __ballot_sync(0xffffffffu, word != 0u);

    int   nk = 0;
    float kx1 = 0, ky1 = 0, kx2 = 0, ky2 = 0, ka = 0;

    while (ne) {                                      // ascending word = rank order
        int w = __ffs(ne) - 1;
        ne &= ne - 1;
        unsigned m = __shfl_sync(0xffffffffu, word, w);

        while (m) {
            int li = __ffs(m) - 1;
            m &= m - 1;
            int ri = w * 32 + li;
            int o  = b * MAXC + ri;

            float qx1 = __ldg(&g_nx1[o]), qy1 = __ldg(&g_ny1[o]);
            float qx2 = __ldg(&g_nx2[o]), qy2 = __ldg(&g_ny2[o]);
            float qa  = __ldg(&g_na[o]);

            int sup = 0;
            if (lane < nk) {
                float ltx = fmaxf(kx1, qx1);
                float lty = fmaxf(ky1, qy1);
                float rbx = fminf(kx2, qx2);
                float rby = fminf(ky2, qy2);
                float ww  = fmaxf(__fsub_rn(rbx, ltx), 0.0f);
                float hh  = fmaxf(__fsub_rn(rby, lty), 0.0f);
                float inter = __fmul_rn(ww, hh);
                float den = __fadd_rn(__fsub_rn(__fadd_rn(ka, qa), inter), 1e-7f);
                sup = (__fdiv_rn(inter, den) > IOU_T) ? 1 : 0;
            }
            unsigned sb = __ballot_sync(0xffffffffu, sup);

            if (!sb) {
                if (lane == nk) { kx1 = qx1; ky1 = qy1; kx2 = qx2; ky2 = qy2; ka = qa; }
                nk++;
                if (lane == 0) {
                    float* rs = out + (size_t)o * 6;
                    rs[0] = __ldg(&g_bx1[o]); rs[1] = __ldg(&g_by1[o]);
                    rs[2] = __ldg(&g_bx2[o]); rs[3] = __ldg(&g_by2[o]);
                    rs[4] = __ldg(&g_conf[o]);
                    rs[5] = (float)c;
                    out[(size_t)BATCH * MAXC * 6 + o] = 1.0f;
                }
            } else {
                if (lane == 0) {
                    float* rs = out + (size_t)o * 6;
                    rs[0] = 0.f; rs[1] = 0.f; rs[2] = 0.f;
                    rs[3] = 0.f; rs[4] = 0.f; rs[5] = 0.f;
                    out[(size_t)BATCH * MAXC * 6 + o] = 0.f;
                }
            }
        }
    }
}

// ---------------- launch ----------------
extern "C" void kernel_launch(void* const* d_in, const int* in_sizes, int n_in,
                              void* d_out, int out_size)
{
    (void)in_sizes; (void)n_in; (void)out_size;
    const float* pred = (const float*)d_in[0];
    float* out = (float*)d_out;

    k_score<<<(BATCH * NANCH) / SAPB, SAPB>>>(pred);   // 3150 blocks
    k_prep<<<BATCH, 1024>>>(out);
    k_nms<<<BATCH * (NCLS / CPB), CPB * 32>>>(out);
}

// round 9
// speedup vs baseline: 1.3945x; 1.1476x over previous
#include <cuda_runtime.h>
#include <stdint.h>

#define BATCH   16
#define NANCH   25200
#define NCLS    80
#define STRIDE  85
#define MAXC    1000
#define CONF_T  0.25f
#define IOU_T   0.45f
#define BINS    4096
#define SLOTCAP 64      // max entries per (batch,bin) bucket
#define SAPB    128     // anchors per block in k_score
#define STHREADS 512    // 4 threads per anchor
#define CPB     8       // classes per block in k_nms

// ---------------- scratch (no allocations allowed) ----------------
__device__ __align__(16) unsigned int g_hist[BATCH * BINS];   // zero-init; re-zeroed each run
__device__ unsigned long long g_bkey[BATCH * BINS * SLOTCAP]; // per-bin key buckets
__device__ float4             g_bbox[BATCH * BINS * SLOTCAP]; // per-bin raw xywh

// per-rank candidate data, [BATCH][MAXC]
__device__ float g_nx1[BATCH * MAXC], g_ny1[BATCH * MAXC];    // offset boxes
__device__ float g_nx2[BATCH * MAXC], g_ny2[BATCH * MAXC];
__device__ float g_na [BATCH * MAXC];                         // offset areas
__device__ float g_bx1[BATCH * MAXC], g_by1[BATCH * MAXC];    // raw boxes
__device__ float g_bx2[BATCH * MAXC], g_by2[BATCH * MAXC];
__device__ float g_conf[BATCH * MAXC];
__device__ unsigned int g_mask[BATCH * NCLS * 32];            // per-class rank bitmasks

// ---------------- K1: quad-per-anchor score/argmax -> global bin buckets ----
__global__ void __launch_bounds__(STHREADS) k_score(const float* __restrict__ pred)
{
    __shared__ __align__(16) float s[SAPB * STRIDE];   // 43520 B

    int tid = threadIdx.x;
    int ga0 = blockIdx.x * SAPB;

    // coalesced float4 staging: 2720 float4s over 512 threads
    const float4* src = (const float4*)(pred + (size_t)ga0 * STRIDE);
    float4*       dst = (float4*)s;
#pragma unroll
    for (int k = 0; k < 5; ++k)
        dst[tid + k * STHREADS] = __ldg(src + tid + k * STHREADS);
    if (tid < (SAPB * STRIDE) / 4 - 5 * STHREADS)      // 2720 - 2560 = 160
        dst[tid + 5 * STHREADS] = __ldg(src + tid + 5 * STHREADS);
    __syncthreads();

    int a = tid >> 2;          // anchor within block (0..127)
    int h = tid & 3;           // quad lane: classes [20h, 20h+20)
    int base = a * STRIDE;

    float obj = s[base + 4];   // same value across the quad -> uniform branch
    if (obj > CONF_T) {
        float bv = -1.0f; int bc = 0x7fffffff;
        int c0 = 5 + h * 20;
#pragma unroll
        for (int ci = 0; ci < 20; ++ci) {
            float p = __fmul_rn(s[base + c0 + ci], obj);    // first-argmax (strict >)
            if (p > bv) { bv = p; bc = h * 20 + ci; }
        }
        // quad combine: bigger value wins; exact tie -> smaller class index.
        // (each half's bc is its first max, so this yields the global first-argmax)
#pragma unroll
        for (int off = 1; off < 4; off <<= 1) {
            float obv = __shfl_xor_sync(0xffffffffu, bv, off);
            int   obc = __shfl_xor_sync(0xffffffffu, bc, off);
            if (obv > bv || (obv == bv && obc < bc)) { bv = obv; bc = obc; }
        }

        if (h == 0 && bv > CONF_T) {
            unsigned bits = __float_as_uint(bv);
            // score in (0.25,1): bits in (0x3E800000,0x3F800000) -> 4096 exact bins
            int bin = (int)(bits >> 12) - 0x3E800;
            bin = bin < 0 ? 0 : (bin > BINS - 1 ? BINS - 1 : bin);

            int ga = ga0 + a;
            int b  = ga / NANCH;
            int n  = ga - b * NANCH;

            unsigned slot = atomicAdd(&g_hist[b * BINS + bin], 1u);
            if (slot < SLOTCAP) {
                size_t sl = (size_t)(b * BINS + bin) * SLOTCAP + slot;
                // key = score_bits:32 | (0x7FFF-idx):15 | cls:8 (idx unique -> cls inert)
                g_bkey[sl] = ((unsigned long long)bits << 32)
                           | ((unsigned long long)(0x7FFFu - (unsigned)n) << 8)
                           | (unsigned long long)(unsigned)bc;
                g_bbox[sl] = make_float4(s[base + 0], s[base + 1],
                                         s[base + 2], s[base + 3]);
            }
        }
    }
}

// helper: per-lane candidate finalize (rank -> global arrays + masks)
__device__ __forceinline__ void emit_candidate(
    int b, unsigned long long key, int rank, size_t slot,
    unsigned int* sMask, unsigned int* sFill)
{
    if (rank >= MAXC) return;
    unsigned bits = (unsigned)(key >> 32);
    int      cls  = (int)(key & 0xFF);
    float4   bx   = __ldg(&g_bbox[slot]);

    float hw = __fmul_rn(bx.z, 0.5f), hh = __fmul_rn(bx.w, 0.5f);
    float bx1 = __fsub_rn(bx.x, hw), by1 = __fsub_rn(bx.y, hh);
    float bx2 = __fadd_rn(bx.x, hw), by2 = __fadd_rn(bx.y, hh);
    float offc = __fmul_rn((float)cls, 4096.0f);      // exact (pow2)
    float ox1 = __fadd_rn(bx1, offc), oy1 = __fadd_rn(by1, offc);
    float ox2 = __fadd_rn(bx2, offc), oy2 = __fadd_rn(by2, offc);
    float area = __fmul_rn(__fsub_rn(ox2, ox1), __fsub_rn(oy2, oy1));

    int o = b * MAXC + rank;
    g_nx1[o] = ox1; g_ny1[o] = oy1; g_nx2[o] = ox2; g_ny2[o] = oy2;
    g_na[o]  = area;
    g_bx1[o] = bx1; g_by1[o] = by1; g_bx2[o] = bx2; g_by2[o] = by2;
    g_conf[o] = __uint_as_float(bits);
    atomicOr(&sMask[cls * 32 + (rank >> 5)], 1u << (rank & 31));
    atomicOr(&sFill[rank >> 5], 1u << (rank & 31));
}

// ---------------- K2: prep — suffix sums, threshold, register ranking -------
__global__ void __launch_bounds__(1024) k_prep(float* __restrict__ out)
{
    int b    = blockIdx.x;
    int t    = threadIdx.x;
    int wrp  = t >> 5;
    int lane = t & 31;

    __shared__ unsigned short sSufB[BINS];        // count of candidates in bins >= bin
    __shared__ unsigned int   sMask[NCLS * 32];   // per-class rank bitmasks
    __shared__ unsigned int   sFill[32];
    __shared__ unsigned int   sWarp[32];
    __shared__ int sT;

    // ---- A: vector load 4 bins, zero global hist (graph-replay invariant) ----
    uint4 hv = *(const uint4*)&g_hist[b * BINS + 4 * t];
    *(uint4*)&g_hist[b * BINS + 4 * t] = make_uint4(0u, 0u, 0u, 0u);

    if (t == 0) sT = BINS;
    if (t < 32) sFill[t] = 0u;
    for (int i = t; i < NCLS * 32; i += 1024) sMask[i] = 0u;

    // ---- B: suffix sums via shuffle scan ----
    unsigned int csum = hv.x + hv.y + hv.z + hv.w;
    unsigned int v = csum;
#pragma unroll
    for (int off = 1; off < 32; off <<= 1) {
        unsigned int u = __shfl_down_sync(0xffffffffu, v, off);
        if (lane + off < 32) v += u;
    }
    if (lane == 0) sWarp[wrp] = v;
    __syncthreads();
    if (wrp == 0) {
        unsigned int w = sWarp[lane];
        unsigned int ws = w;
#pragma unroll
        for (int off = 1; off < 32; off <<= 1) {
            unsigned int u = __shfl_down_sync(0xffffffffu, ws, off);
            if (lane + off < 32) ws += u;
        }
        sWarp[lane] = ws - w;                     // exclusive (warps above)
    }
    __syncthreads();
    {
        unsigned int chunkSuf = v + sWarp[wrp];   // count in bins >= 4t
        sSufB[4 * t + 0] = (unsigned short)chunkSuf;
        sSufB[4 * t + 1] = (unsigned short)(chunkSuf - hv.x);
        sSufB[4 * t + 2] = (unsigned short)(chunkSuf - hv.x - hv.y);
        sSufB[4 * t + 3] = (unsigned short)(chunkSuf - hv.x - hv.y - hv.z);
    }
    __syncthreads();

    // ---- C: threshold bin T (parallel over bins) ----
    unsigned int total = sSufB[0];
    unsigned int K = total < MAXC ? total : MAXC;
    if (K > 0) {
#pragma unroll
        for (int k = 0; k < 4; ++k) {
            int bi = 4 * t + k;
            unsigned int hi = sSufB[bi];
            unsigned int lo = (bi + 1 < BINS) ? sSufB[bi + 1] : 0u;
            if (hi >= K && lo < K) sT = bi;       // unique writer
        }
    }
    __syncthreads();
    int T = sT;

    // ---- DE: warp-per-bin register ranking + candidate emit ----
    for (int bin = T + wrp; bin < BINS; bin += 32) {
        unsigned int off = (bin + 1 < BINS) ? sSufB[bin + 1] : 0u;
        int cb = (int)sSufB[bin] - (int)off;
        if (cb <= 0) continue;
        if (cb > SLOTCAP) cb = SLOTCAP;

        size_t sb = (size_t)(b * BINS + bin) * SLOTCAP;
        unsigned long long k1 = (lane < cb)      ? __ldg(&g_bkey[sb + lane])      : 0ull;
        unsigned long long k2 = (32 + lane < cb) ? __ldg(&g_bkey[sb + 32 + lane]) : 0ull;

        int n1 = cb < 32 ? cb : 32;
        int n2 = cb - n1;
        int r1 = 0, r2 = 0;
        for (int j = 0; j < n1; ++j) {
            unsigned long long kj = __shfl_sync(0xffffffffu, k1, j);
            r1 += (kj > k1) ? 1 : 0;
            r2 += (kj > k2) ? 1 : 0;
        }
        for (int j = 0; j < n2; ++j) {
            unsigned long long kj = __shfl_sync(0xffffffffu, k2, j);
            r1 += (kj > k1) ? 1 : 0;
            r2 += (kj > k2) ? 1 : 0;
        }

        if (lane < cb)      emit_candidate(b, k1, (int)off + r1, sb + lane,      sMask, sFill);
        if (32 + lane < cb) emit_candidate(b, k2, (int)off + r2, sb + 32 + lane, sMask, sFill);
    }
    __syncthreads();

    // ---- F: copy masks to global; zero rows for empty ranks ----
    for (int i = t; i < NCLS * 32; i += 1024)
        g_mask[b * NCLS * 32 + i] = sMask[i];

    for (int r = t; r < MAXC; r += 1024) {
        if (!((sFill[r >> 5] >> (r & 31)) & 1u)) {
            int o = b * MAXC + r;
            float2* row = (float2*)(out + (size_t)o * 6);
            row[0] = make_float2(0.f, 0.f);
            row[1] = make_float2(0.f, 0.f);
            row[2] = make_float2(0.f, 0.f);
            out[(size_t)BATCH * MAXC * 6 + o] = 0.f;
        }
    }
}

// ---------------- K3: per-(batch,class) greedy NMS, warp per class ----------
// Cross-class IoU is exactly 0 (class offsets are multiples of 4096, raw boxes
// in [-0.5,1.5]) -> reference greedy loop decomposes by class.
__global__ void __launch_bounds__(CPB * 32) k_nms(float* __restrict__ out)
{
    const int BLOCKS_PER_B = NCLS / CPB;              // 10
    int b    = blockIdx.x / BLOCKS_PER_B;
    int wrp  = threadIdx.x >> 5;
    int lane = threadIdx.x & 31;
    int c    = (blockIdx.x % BLOCKS_PER_B) * CPB + wrp;

    unsigned word = __ldg(&g_mask[(b * NCLS + c) * 32 + lane]);
    unsigned ne   = __ballot_sync(0xffffffffu, word != 0u);

    int   nk = 0;
    float kx1 = 0, ky1 = 0, kx2 = 0, ky2 = 0, ka = 0;

    while (ne) {                                      // ascending word = rank order
        int w = __ffs(ne) - 1;
        ne &= ne - 1;
        unsigned m = __shfl_sync(0xffffffffu, word, w);

        while (m) {
            int li = __ffs(m) - 1;
            m &= m - 1;
            int ri = w * 32 + li;
            int o  = b * MAXC + ri;

            float qx1 = __ldg(&g_nx1[o]), qy1 = __ldg(&g_ny1[o]);
            float qx2 = __ldg(&g_nx2[o]), qy2 = __ldg(&g_ny2[o]);
            float qa  = __ldg(&g_na[o]);

            int sup = 0;
            if (lane < nk) {
                float ltx = fmaxf(kx1, qx1);
                float lty = fmaxf(ky1, qy1);
                float rbx = fminf(kx2, qx2);
                float rby = fminf(ky2, qy2);
                float ww  = fmaxf(__fsub_rn(rbx, ltx), 0.0f);
                float hh  = fmaxf(__fsub_rn(rby, lty), 0.0f);
                float inter = __fmul_rn(ww, hh);
                float den = __fadd_rn(__fsub_rn(__fadd_rn(ka, qa), inter), 1e-7f);
                sup = (__fdiv_rn(inter, den) > IOU_T) ? 1 : 0;
            }
            unsigned sb = __ballot_sync(0xffffffffu, sup);

            if (!sb) {
                if (lane == nk) { kx1 = qx1; ky1 = qy1; kx2 = qx2; ky2 = qy2; ka = qa; }
                nk++;
                if (lane == 0) {
                    float* rs = out + (size_t)o * 6;
                    rs[0] = __ldg(&g_bx1[o]); rs[1] = __ldg(&g_by1[o]);
                    rs[2] = __ldg(&g_bx2[o]); rs[3] = __ldg(&g_by2[o]);
                    rs[4] = __ldg(&g_conf[o]);
                    rs[5] = (float)c;
                    out[(size_t)BATCH * MAXC * 6 + o] = 1.0f;
                }
            } else {
                if (lane == 0) {
                    float* rs = out + (size_t)o * 6;
                    rs[0] = 0.f; rs[1] = 0.f; rs[2] = 0.f;
                    rs[3] = 0.f; rs[4] = 0.f; rs[5] = 0.f;
                    out[(size_t)BATCH * MAXC * 6 + o] = 0.f;
                }
            }
        }
    }
}

// ---------------- launch ----------------
extern "C" void kernel_launch(void* const* d_in, const int* in_sizes, int n_in,
                              void* d_out, int out_size)
{
    (void)in_sizes; (void)n_in; (void)out_size;
    const float* pred = (const float*)d_in[0];
    float* out = (float*)d_out;

    k_score<<<(BATCH * NANCH) / SAPB, STHREADS>>>(pred);   // 3150 blocks x 512
    k_prep<<<BATCH, 1024>>>(out);
    k_nms<<<BATCH * (NCLS / CPB), CPB * 32>>>(out);
}

// round 10
// speedup vs baseline: 1.8932x; 1.3575x over previous
#include <cuda_runtime.h>
#include <stdint.h>

#define BATCH   16
#define NANCH   25200
#define NCLS    80
#define STRIDE  85
#define MAXC    1000
#define CONF_T  0.25f
#define IOU_T   0.45f
#define BINS    4096
#define SLOTCAP 64      // max entries per (batch,bin) bucket
#define SAPB    128     // anchors per block in k_score
#define STHREADS 512    // 4 threads per anchor
#define CPB     8       // classes per block in k_nms
#define PSLICE  8       // CTAs per batch in k_prep

// ---------------- scratch (no allocations allowed) ----------------
__device__ __align__(16) unsigned int g_hist[BATCH * BINS];   // zero-init; zeroed in k_nms
__device__ unsigned long long g_bkey[BATCH * BINS * SLOTCAP]; // per-bin key buckets
__device__ float4             g_bbox[BATCH * BINS * SLOTCAP]; // per-bin raw xywh

// per-rank candidate data, [BATCH][MAXC]
__device__ float4 g_nbox[BATCH * MAXC];                       // offset box x1,y1,x2,y2
__device__ float  g_na  [BATCH * MAXC];                       // offset area
__device__ float4 g_rbox[BATCH * MAXC];                       // raw box x1,y1,x2,y2
__device__ float  g_conf[BATCH * MAXC];
__device__ unsigned int g_mask[BATCH * NCLS * 32];            // per-class rank bitmasks (zeroed in k_nms)
__device__ int    g_cnt[BATCH];                               // candidate count per batch

// ---------------- K1: quad-per-anchor score/argmax -> global bin buckets ----
__global__ void __launch_bounds__(STHREADS) k_score(const float* __restrict__ pred)
{
    __shared__ __align__(16) float s[SAPB * STRIDE];   // 43520 B

    int tid = threadIdx.x;
    int ga0 = blockIdx.x * SAPB;

    const float4* src = (const float4*)(pred + (size_t)ga0 * STRIDE);
    float4*       dst = (float4*)s;
#pragma unroll
    for (int k = 0; k < 5; ++k)
        dst[tid + k * STHREADS] = __ldg(src + tid + k * STHREADS);
    if (tid < (SAPB * STRIDE) / 4 - 5 * STHREADS)      // 2720 - 2560 = 160
        dst[tid + 5 * STHREADS] = __ldg(src + tid + 5 * STHREADS);
    __syncthreads();

    int a = tid >> 2;          // anchor within block
    int h = tid & 3;           // quad lane: classes [20h, 20h+20)
    int base = a * STRIDE;

    float obj = s[base + 4];   // uniform across the quad
    if (obj > CONF_T) {
        float bv = -1.0f; int bc = 0x7fffffff;
        int c0 = 5 + h * 20;
#pragma unroll
        for (int ci = 0; ci < 20; ++ci) {
            float p = __fmul_rn(s[base + c0 + ci], obj);    // first-argmax (strict >)
            if (p > bv) { bv = p; bc = h * 20 + ci; }
        }
        // quad combine: bigger value wins; exact tie -> smaller class index
#pragma unroll
        for (int off = 1; off < 4; off <<= 1) {
            float obv = __shfl_xor_sync(0xffffffffu, bv, off);
            int   obc = __shfl_xor_sync(0xffffffffu, bc, off);
            if (obv > bv || (obv == bv && obc < bc)) { bv = obv; bc = obc; }
        }

        if (h == 0 && bv > CONF_T) {
            unsigned bits = __float_as_uint(bv);
            // score in (0.25,1): bits in (0x3E800000,0x3F800000) -> 4096 exact bins
            int bin = (int)(bits >> 12) - 0x3E800;
            bin = bin < 0 ? 0 : (bin > BINS - 1 ? BINS - 1 : bin);

            int ga = ga0 + a;
            int b  = ga / NANCH;
            int n  = ga - b * NANCH;

            unsigned slot = atomicAdd(&g_hist[b * BINS + bin], 1u);
            if (slot < SLOTCAP) {
                size_t sl = (size_t)(b * BINS + bin) * SLOTCAP + slot;
                // key = score_bits:32 | (0x7FFF-idx):15 | cls:8 (idx unique -> cls inert)
                g_bkey[sl] = ((unsigned long long)bits << 32)
                           | ((unsigned long long)(0x7FFFu - (unsigned)n) << 8)
                           | (unsigned long long)(unsigned)bc;
                g_bbox[sl] = make_float4(s[base + 0], s[base + 1],
                                         s[base + 2], s[base + 3]);
            }
        }
    }
}

// per-lane candidate finalize (rank -> global arrays + mask)
__device__ __forceinline__ void emit_candidate(
    int b, unsigned long long key, int rank, size_t slot)
{
    if (rank >= MAXC) return;
    unsigned bits = (unsigned)(key >> 32);
    int      cls  = (int)(key & 0xFF);
    float4   bx   = __ldg(&g_bbox[slot]);

    float hw = __fmul_rn(bx.z, 0.5f), hh = __fmul_rn(bx.w, 0.5f);
    float bx1 = __fsub_rn(bx.x, hw), by1 = __fsub_rn(bx.y, hh);
    float bx2 = __fadd_rn(bx.x, hw), by2 = __fadd_rn(bx.y, hh);
    float offc = __fmul_rn((float)cls, 4096.0f);      // exact (pow2)
    float ox1 = __fadd_rn(bx1, offc), oy1 = __fadd_rn(by1, offc);
    float ox2 = __fadd_rn(bx2, offc), oy2 = __fadd_rn(by2, offc);
    float area = __fmul_rn(__fsub_rn(ox2, ox1), __fsub_rn(oy2, oy1));

    int o = b * MAXC + rank;
    g_nbox[o] = make_float4(ox1, oy1, ox2, oy2);
    g_na[o]   = area;
    g_rbox[o] = make_float4(bx1, by1, bx2, by2);
    g_conf[o] = __uint_as_float(bits);
    atomicOr(&g_mask[(b * NCLS + cls) * 32 + (rank >> 5)], 1u << (rank & 31));
}

// ---------------- K2: prep — redundant scan, sliced ranking/emit ------------
__global__ void __launch_bounds__(1024) k_prep()
{
    int b     = blockIdx.x / PSLICE;
    int slice = blockIdx.x % PSLICE;
    int t     = threadIdx.x;
    int wrp   = t >> 5;
    int lane  = t & 31;

    __shared__ unsigned short sSufB[BINS];    // count of candidates in bins >= bin
    __shared__ unsigned int   sWarp[32];
    __shared__ int sT;

    // ---- A: load hist (NOT zeroed here — other slices still read it) ----
    uint4 hv = *(const uint4*)&g_hist[b * BINS + 4 * t];
    if (t == 0) sT = BINS;

    // ---- B: suffix sums via shuffle scan ----
    unsigned int csum = hv.x + hv.y + hv.z + hv.w;
    unsigned int v = csum;
#pragma unroll
    for (int off = 1; off < 32; off <<= 1) {
        unsigned int u = __shfl_down_sync(0xffffffffu, v, off);
        if (lane + off < 32) v += u;
    }
    if (lane == 0) sWarp[wrp] = v;
    __syncthreads();
    if (wrp == 0) {
        unsigned int w = sWarp[lane];
        unsigned int ws = w;
#pragma unroll
        for (int off = 1; off < 32; off <<= 1) {
            unsigned int u = __shfl_down_sync(0xffffffffu, ws, off);
            if (lane + off < 32) ws += u;
        }
        sWarp[lane] = ws - w;                 // exclusive (warps above)
    }
    __syncthreads();
    {
        unsigned int chunkSuf = v + sWarp[wrp];
        sSufB[4 * t + 0] = (unsigned short)chunkSuf;
        sSufB[4 * t + 1] = (unsigned short)(chunkSuf - hv.x);
        sSufB[4 * t + 2] = (unsigned short)(chunkSuf - hv.x - hv.y);
        sSufB[4 * t + 3] = (unsigned short)(chunkSuf - hv.x - hv.y - hv.z);
    }
    __syncthreads();

    // ---- C: threshold bin T ----
    unsigned int total = sSufB[0];
    unsigned int K = total < MAXC ? total : MAXC;
    if (K > 0) {
#pragma unroll
        for (int k = 0; k < 4; ++k) {
            int bi = 4 * t + k;
            unsigned int hi = sSufB[bi];
            unsigned int lo = (bi + 1 < BINS) ? sSufB[bi + 1] : 0u;
            if (hi >= K && lo < K) sT = bi;
        }
    }
    __syncthreads();
    int T = sT;

    if (slice == 0 && t == 0)
        g_cnt[b] = (T < BINS) ? (int)sSufB[T] : 0;

    // ---- DE: warp-per-bin register ranking + emit (1/PSLICE of bins) ----
    for (int bin = T + slice * 32 + wrp; bin < BINS; bin += 32 * PSLICE) {
        unsigned int off = (bin + 1 < BINS) ? sSufB[bin + 1] : 0u;
        int cb = (int)sSufB[bin] - (int)off;
        if (cb <= 0) continue;
        if (cb > SLOTCAP) cb = SLOTCAP;

        size_t sb = (size_t)(b * BINS + bin) * SLOTCAP;
        unsigned long long k1 = (lane < cb)      ? __ldg(&g_bkey[sb + lane])      : 0ull;
        unsigned long long k2 = (32 + lane < cb) ? __ldg(&g_bkey[sb + 32 + lane]) : 0ull;

        int n1 = cb < 32 ? cb : 32;
        int n2 = cb - n1;
        int r1 = 0, r2 = 0;
        for (int j = 0; j < n1; ++j) {
            unsigned long long kj = __shfl_sync(0xffffffffu, k1, j);
            r1 += (kj > k1) ? 1 : 0;
            r2 += (kj > k2) ? 1 : 0;
        }
        for (int j = 0; j < n2; ++j) {
            unsigned long long kj = __shfl_sync(0xffffffffu, k2, j);
            r1 += (kj > k1) ? 1 : 0;
            r2 += (kj > k2) ? 1 : 0;
        }

        if (lane < cb)      emit_candidate(b, k1, (int)off + r1, sb + lane);
        if (32 + lane < cb) emit_candidate(b, k2, (int)off + r2, sb + 32 + lane);
    }
}

// ---------------- K3: per-(batch,class) greedy NMS + housekeeping -----------
// Cross-class IoU is exactly 0 (class offsets are multiples of 4096, raw boxes
// in [-0.5,1.5]) -> reference greedy loop decomposes by class.
__global__ void __launch_bounds__(CPB * 32) k_nms(float* __restrict__ out)
{
    const int BLOCKS_PER_B = NCLS / CPB;              // 10
    int b    = blockIdx.x / BLOCKS_PER_B;
    int s    = blockIdx.x % BLOCKS_PER_B;
    int tid  = threadIdx.x;
    int wrp  = tid >> 5;
    int lane = tid & 31;
    int c    = s * CPB + wrp;

    __shared__ unsigned short sList[CPB][MAXC];       // 16000 B

    // housekeeping 1: zero this block's slice of g_hist (replay invariant)
    {
        int lo = s * 410;
        int hi = lo + 410; if (hi > BINS) hi = BINS;
        for (int i = lo + tid; i < hi; i += CPB * 32)
            g_hist[b * BINS + i] = 0u;
    }
    // housekeeping 2: zero rows for empty ranks (ranks are contiguous 0..cnt-1)
    int cnt = __ldg(&g_cnt[b]);
    {
        int start = cnt < MAXC ? cnt : MAXC;
        for (int r = start + s * (CPB * 32) + tid; r < MAXC; r += BLOCKS_PER_B * CPB * 32) {
            int o = b * MAXC + r;
            float2* row = (float2*)(out + (size_t)o * 6);
            row[0] = make_float2(0.f, 0.f);
            row[1] = make_float2(0.f, 0.f);
            row[2] = make_float2(0.f, 0.f);
            out[(size_t)BATCH * MAXC * 6 + o] = 0.f;
        }
    }

    // ---- gather: mask -> rank list in SMEM (and reset mask for replay) ----
    int mi = (b * NCLS + c) * 32 + lane;
    unsigned word = __ldg(&g_mask[mi]);
    g_mask[mi] = 0u;

    int pc = __popc(word);
    int incl = pc;
#pragma unroll
    for (int off = 1; off < 32; off <<= 1) {
        int u = __shfl_up_sync(0xffffffffu, incl, off);
        if (lane >= off) incl += u;
    }
    int excl  = incl - pc;
    int total = __shfl_sync(0xffffffffu, incl, 31);

    {
        unsigned m = word; int o = excl;
        while (m) {
            int p = __ffs(m) - 1;
            m &= m - 1;
            sList[wrp][o++] = (unsigned short)(lane * 32 + p);
        }
    }
    __syncwarp();

    // ---- greedy NMS: prefetch chunk to registers, serial loop on shuffles ----
    int   nk = 0;
    float kx1 = 0, ky1 = 0, kx2 = 0, ky2 = 0, ka = 0;

    for (int base = 0; base < total; base += 32) {
        int j = base + lane;
        int ri = 0;
        float4 qb = make_float4(0.f, 0.f, 0.f, 0.f);
        float  qa_ = 0.f;
        if (j < total) {
            ri = (int)sList[wrp][j];
            int o = b * MAXC + ri;
            qb  = __ldg(&g_nbox[o]);
            qa_ = __ldg(&g_na[o]);
        }
        int nl = total - base; if (nl > 32) nl = 32;
        int keptflag = 0;

        for (int k = 0; k < nl; ++k) {
            float qx1 = __shfl_sync(0xffffffffu, qb.x, k);
            float qy1 = __shfl_sync(0xffffffffu, qb.y, k);
            float qx2 = __shfl_sync(0xffffffffu, qb.z, k);
            float qy2 = __shfl_sync(0xffffffffu, qb.w, k);
            float qa  = __shfl_sync(0xffffffffu, qa_,  k);

            int sup = 0;
            if (lane < nk) {
                float ltx = fmaxf(kx1, qx1);
                float lty = fmaxf(ky1, qy1);
                float rbx = fminf(kx2, qx2);
                float rby = fminf(ky2, qy2);
                float ww  = fmaxf(__fsub_rn(rbx, ltx), 0.0f);
                float hh  = fmaxf(__fsub_rn(rby, lty), 0.0f);
                float inter = __fmul_rn(ww, hh);
                float den = __fadd_rn(__fsub_rn(__fadd_rn(ka, qa), inter), 1e-7f);
                sup = (__fdiv_rn(inter, den) > IOU_T) ? 1 : 0;
            }
            unsigned sb = __ballot_sync(0xffffffffu, sup);
            if (!sb) {
                if (lane == nk) { kx1 = qx1; ky1 = qy1; kx2 = qx2; ky2 = qy2; ka = qa; }
                nk++;
                if (lane == k) keptflag = 1;
            }
        }

        // owning lane writes its output row (outside the dependent chain)
        if (j < total) {
            int o = b * MAXC + ri;
            float* rs = out + (size_t)o * 6;
            if (keptflag) {
                float4 rb = __ldg(&g_rbox[o]);
                rs[0] = rb.x; rs[1] = rb.y; rs[2] = rb.z; rs[3] = rb.w;
                rs[4] = __ldg(&g_conf[o]);
                rs[5] = (float)c;
                out[(size_t)BATCH * MAXC * 6 + o] = 1.0f;
            } else {
                rs[0] = 0.f; rs[1] = 0.f; rs[2] = 0.f;
                rs[3] = 0.f; rs[4] = 0.f; rs[5] = 0.f;
                out[(size_t)BATCH * MAXC * 6 + o] = 0.f;
            }
        }
    }
}

// ---------------- launch ----------------
extern "C" void kernel_launch(void* const* d_in, const int* in_sizes, int n_in,
                              void* d_out, int out_size)
{
    (void)in_sizes; (void)n_in; (void)out_size;
    const float* pred = (const float*)d_in[0];
    float* out = (float*)d_out;

    k_score<<<(BATCH * NANCH) / SAPB, STHREADS>>>(pred);   // 3150 blocks x 512
    k_prep<<<BATCH * PSLICE, 1024>>>();                    // 128 blocks
    k_nms<<<BATCH * (NCLS / CPB), CPB * 32>>>(out);        // 160 blocks
}

// round 11
// speedup vs baseline: 1.9948x; 1.0537x over previous
#include <cuda_runtime.h>
#include <stdint.h>

#define BATCH   16
#define NANCH   25200
#define NCLS    80
#define STRIDE  85
#define MAXC    1000
#define CONF_T  0.25f
#define IOU_T   0.45f
#define BINS    4096
#define SLOTCAP 64      // max entries per (batch,bin) bucket
#define SAPB    128     // anchors per block in k_score
#define STHREADS 512    // 4 threads per anchor
#define CPB     8       // classes per block in k_nms
#define PSLICE  8       // CTAs per batch in k_prep
#define TILE_BYTES (SAPB * STRIDE * 4)   // 43520

// ---------------- scratch (no allocations allowed) ----------------
__device__ __align__(16) unsigned int g_hist[BATCH * BINS];   // zero-init; zeroed in k_nms
__device__ unsigned long long g_bkey[BATCH * BINS * SLOTCAP]; // per-bin key buckets
__device__ float4             g_bbox[BATCH * BINS * SLOTCAP]; // per-bin raw xywh

// per-rank candidate data, [BATCH][MAXC]
__device__ float4 g_nbox[BATCH * MAXC];                       // offset box x1,y1,x2,y2
__device__ float  g_na  [BATCH * MAXC];                       // offset area
__device__ float4 g_rbox[BATCH * MAXC];                       // raw box x1,y1,x2,y2
__device__ float  g_conf[BATCH * MAXC];
__device__ unsigned int g_mask[BATCH * NCLS * 32];            // per-class rank bitmasks (zeroed in k_nms)
__device__ int    g_cnt[BATCH];                               // candidate count per batch

__device__ __forceinline__ unsigned smem_u32(const void* p)
{
    unsigned a;
    asm("{ .reg .u64 t; cvta.to.shared.u64 t, %1; cvt.u32.u64 %0, t; }"
        : "=r"(a) : "l"(p));
    return a;
}

// ---------------- K1: TMA bulk stage + quad-per-anchor score/argmax ---------
__global__ void __launch_bounds__(STHREADS) k_score(const float* __restrict__ pred)
{
    __shared__ __align__(16) float s[SAPB * STRIDE];   // 43520 B
    __shared__ __align__(8)  unsigned long long sBar;

    int tid = threadIdx.x;
    int ga0 = blockIdx.x * SAPB;

    unsigned smem_base = smem_u32(s);
    unsigned bar       = smem_u32(&sBar);

    // TMA bulk copy: global -> SMEM, bypassing L1 and the register file
    if (tid == 0) {
        asm volatile("mbarrier.init.shared.b64 [%0], %1;"
                     :: "r"(bar), "r"(1) : "memory");
        // fence so the TMA engine sees the initialized barrier
        asm volatile("fence.proxy.async.shared::cta;" ::: "memory");
        asm volatile("mbarrier.arrive.expect_tx.shared.b64 _, [%0], %1;"
                     :: "r"(bar), "r"(TILE_BYTES) : "memory");
        asm volatile(
            "cp.async.bulk.shared::cluster.global.mbarrier::complete_tx::bytes "
            "[%0], [%1], %2, [%3];"
            :: "r"(smem_base), "l"(pred + (size_t)ga0 * STRIDE),
               "r"(TILE_BYTES), "r"(bar) : "memory");
    }
    __syncthreads();   // all threads see initialized barrier before waiting

    // wait for TMA completion (parity 0)
    asm volatile(
        "{\n\t"
        ".reg .pred P;\n\t"
        "WAIT_%=:\n\t"
        "mbarrier.try_wait.parity.shared.b64 P, [%0], %1;\n\t"
        "@P bra DONE_%=;\n\t"
        "bra WAIT_%=;\n\t"
        "DONE_%=:\n\t"
        "}"
        :: "r"(bar), "r"(0) : "memory");

    int a = tid >> 2;          // anchor within block
    int h = tid & 3;           // quad lane: classes [20h, 20h+20)
    int base = a * STRIDE;

    float obj = s[base + 4];   // uniform across the quad
    if (obj > CONF_T) {
        float bv = -1.0f; int bc = 0x7fffffff;
        int c0 = 5 + h * 20;
#pragma unroll
        for (int ci = 0; ci < 20; ++ci) {
            float p = __fmul_rn(s[base + c0 + ci], obj);    // first-argmax (strict >)
            if (p > bv) { bv = p; bc = h * 20 + ci; }
        }
        // quad combine: bigger value wins; exact tie -> smaller class index
#pragma unroll
        for (int off = 1; off < 4; off <<= 1) {
            float obv = __shfl_xor_sync(0xffffffffu, bv, off);
            int   obc = __shfl_xor_sync(0xffffffffu, bc, off);
            if (obv > bv || (obv == bv && obc < bc)) { bv = obv; bc = obc; }
        }

        if (h == 0 && bv > CONF_T) {
            unsigned bits = __float_as_uint(bv);
            // score in (0.25,1): bits in (0x3E800000,0x3F800000) -> 4096 exact bins
            int bin = (int)(bits >> 12) - 0x3E800;
            bin = bin < 0 ? 0 : (bin > BINS - 1 ? BINS - 1 : bin);

            int ga = ga0 + a;
            int b  = ga / NANCH;
            int n  = ga - b * NANCH;

            unsigned slot = atomicAdd(&g_hist[b * BINS + bin], 1u);
            if (slot < SLOTCAP) {
                size_t sl = (size_t)(b * BINS + bin) * SLOTCAP + slot;
                // key = score_bits:32 | (0x7FFF-idx):15 | cls:8 (idx unique -> cls inert)
                g_bkey[sl] = ((unsigned long long)bits << 32)
                           | ((unsigned long long)(0x7FFFu - (unsigned)n) << 8)
                           | (unsigned long long)(unsigned)bc;
                g_bbox[sl] = make_float4(s[base + 0], s[base + 1],
                                         s[base + 2], s[base + 3]);
            }
        }
    }
}

// per-lane candidate finalize (rank -> global arrays + mask)
__device__ __forceinline__ void emit_candidate(
    int b, unsigned long long key, int rank, size_t slot)
{
    if (rank >= MAXC) return;
    unsigned bits = (unsigned)(key >> 32);
    int      cls  = (int)(key & 0xFF);
    float4   bx   = __ldg(&g_bbox[slot]);

    float hw = __fmul_rn(bx.z, 0.5f), hh = __fmul_rn(bx.w, 0.5f);
    float bx1 = __fsub_rn(bx.x, hw), by1 = __fsub_rn(bx.y, hh);
    float bx2 = __fadd_rn(bx.x, hw), by2 = __fadd_rn(bx.y, hh);
    float offc = __fmul_rn((float)cls, 4096.0f);      // exact (pow2)
    float ox1 = __fadd_rn(bx1, offc), oy1 = __fadd_rn(by1, offc);
    float ox2 = __fadd_rn(bx2, offc), oy2 = __fadd_rn(by2, offc);
    float area = __fmul_rn(__fsub_rn(ox2, ox1), __fsub_rn(oy2, oy1));

    int o = b * MAXC + rank;
    g_nbox[o] = make_float4(ox1, oy1, ox2, oy2);
    g_na[o]   = area;
    g_rbox[o] = make_float4(bx1, by1, bx2, by2);
    g_conf[o] = __uint_as_float(bits);
    atomicOr(&g_mask[(b * NCLS + cls) * 32 + (rank >> 5)], 1u << (rank & 31));
}

// ---------------- K2: prep — redundant scan, sliced ranking/emit ------------
__global__ void __launch_bounds__(1024) k_prep()
{
    int b     = blockIdx.x / PSLICE;
    int slice = blockIdx.x % PSLICE;
    int t     = threadIdx.x;
    int wrp   = t >> 5;
    int lane  = t & 31;

    __shared__ unsigned short sSufB[BINS];    // count of candidates in bins >= bin
    __shared__ unsigned int   sWarp[32];
    __shared__ int sT;

    // ---- A: load hist (NOT zeroed here — other slices still read it) ----
    uint4 hv = *(const uint4*)&g_hist[b * BINS + 4 * t];
    if (t == 0) sT = BINS;

    // ---- B: suffix sums via shuffle scan ----
    unsigned int csum = hv.x + hv.y + hv.z + hv.w;
    unsigned int v = csum;
#pragma unroll
    for (int off = 1; off < 32; off <<= 1) {
        unsigned int u = __shfl_down_sync(0xffffffffu, v, off);
        if (lane + off < 32) v += u;
    }
    if (lane == 0) sWarp[wrp] = v;
    __syncthreads();
    if (wrp == 0) {
        unsigned int w = sWarp[lane];
        unsigned int ws = w;
#pragma unroll
        for (int off = 1; off < 32; off <<= 1) {
            unsigned int u = __shfl_down_sync(0xffffffffu, ws, off);
            if (lane + off < 32) ws += u;
        }
        sWarp[lane] = ws - w;                 // exclusive (warps above)
    }
    __syncthreads();
    {
        unsigned int chunkSuf = v + sWarp[wrp];
        sSufB[4 * t + 0] = (unsigned short)chunkSuf;
        sSufB[4 * t + 1] = (unsigned short)(chunkSuf - hv.x);
        sSufB[4 * t + 2] = (unsigned short)(chunkSuf - hv.x - hv.y);
        sSufB[4 * t + 3] = (unsigned short)(chunkSuf - hv.x - hv.y - hv.z);
    }
    __syncthreads();

    // ---- C: threshold bin T ----
    unsigned int total = sSufB[0];
    unsigned int K = total < MAXC ? total : MAXC;
    if (K > 0) {
#pragma unroll
        for (int k = 0; k < 4; ++k) {
            int bi = 4 * t + k;
            unsigned int hi = sSufB[bi];
            unsigned int lo = (bi + 1 < BINS) ? sSufB[bi + 1] : 0u;
            if (hi >= K && lo < K) sT = bi;
        }
    }
    __syncthreads();
    int T = sT;

    if (slice == 0 && t == 0)
        g_cnt[b] = (T < BINS) ? (int)sSufB[T] : 0;

    // ---- DE: warp-per-bin register ranking + emit (1/PSLICE of bins) ----
    for (int bin = T + slice * 32 + wrp; bin < BINS; bin += 32 * PSLICE) {
        unsigned int off = (bin + 1 < BINS) ? sSufB[bin + 1] : 0u;
        int cb = (int)sSufB[bin] - (int)off;
        if (cb <= 0) continue;
        if (cb > SLOTCAP) cb = SLOTCAP;

        size_t sb = (size_t)(b * BINS + bin) * SLOTCAP;
        unsigned long long k1 = (lane < cb)      ? __ldg(&g_bkey[sb + lane])      : 0ull;
        unsigned long long k2 = (32 + lane < cb) ? __ldg(&g_bkey[sb + 32 + lane]) : 0ull;

        int n1 = cb < 32 ? cb : 32;
        int n2 = cb - n1;
        int r1 = 0, r2 = 0;
        for (int j = 0; j < n1; ++j) {
            unsigned long long kj = __shfl_sync(0xffffffffu, k1, j);
            r1 += (kj > k1) ? 1 : 0;
            r2 += (kj > k2) ? 1 : 0;
        }
        for (int j = 0; j < n2; ++j) {
            unsigned long long kj = __shfl_sync(0xffffffffu, k2, j);
            r1 += (kj > k1) ? 1 : 0;
            r2 += (kj > k2) ? 1 : 0;
        }

        if (lane < cb)      emit_candidate(b, k1, (int)off + r1, sb + lane);
        if (32 + lane < cb) emit_candidate(b, k2, (int)off + r2, sb + 32 + lane);
    }
}

// ---------------- K3: per-(batch,class) greedy NMS + housekeeping -----------
// Cross-class IoU is exactly 0 (class offsets are multiples of 4096, raw boxes
// in [-0.5,1.5]) -> reference greedy loop decomposes by class.
__global__ void __launch_bounds__(CPB * 32) k_nms(float* __restrict__ out)
{
    const int BLOCKS_PER_B = NCLS / CPB;              // 10
    int b    = blockIdx.x / BLOCKS_PER_B;
    int s    = blockIdx.x % BLOCKS_PER_B;
    int tid  = threadIdx.x;
    int wrp  = tid >> 5;
    int lane = tid & 31;
    int c    = s * CPB + wrp;

    __shared__ unsigned short sList[CPB][MAXC];       // 16000 B

    // housekeeping 1: zero this block's slice of g_hist (replay invariant)
    {
        int lo = s * 410;
        int hi = lo + 410; if (hi > BINS) hi = BINS;
        for (int i = lo + tid; i < hi; i += CPB * 32)
            g_hist[b * BINS + i] = 0u;
    }
    // housekeeping 2: zero rows for empty ranks (ranks are contiguous 0..cnt-1)
    int cnt = __ldg(&g_cnt[b]);
    {
        int start = cnt < MAXC ? cnt : MAXC;
        for (int r = start + s * (CPB * 32) + tid; r < MAXC; r += BLOCKS_PER_B * CPB * 32) {
            int o = b * MAXC + r;
            float2* row = (float2*)(out + (size_t)o * 6);
            row[0] = make_float2(0.f, 0.f);
            row[1] = make_float2(0.f, 0.f);
            row[2] = make_float2(0.f, 0.f);
            out[(size_t)BATCH * MAXC * 6 + o] = 0.f;
        }
    }

    // ---- gather: mask -> rank list in SMEM (and reset mask for replay) ----
    int mi = (b * NCLS + c) * 32 + lane;
    unsigned word = __ldg(&g_mask[mi]);
    g_mask[mi] = 0u;

    int pc = __popc(word);
    int incl = pc;
#pragma unroll
    for (int off = 1; off < 32; off <<= 1) {
        int u = __shfl_up_sync(0xffffffffu, incl, off);
        if (lane >= off) incl += u;
    }
    int excl  = incl - pc;
    int total = __shfl_sync(0xffffffffu, incl, 31);

    {
        unsigned m = word; int o = excl;
        while (m) {
            int p = __ffs(m) - 1;
            m &= m - 1;
            sList[wrp][o++] = (unsigned short)(lane * 32 + p);
        }
    }
    __syncwarp();

    // ---- greedy NMS: prefetch chunk to registers, serial loop on shuffles ----
    int   nk = 0;
    float kx1 = 0, ky1 = 0, kx2 = 0, ky2 = 0, ka = 0;

    for (int base = 0; base < total; base += 32) {
        int j = base + lane;
        int ri = 0;
        float4 qb = make_float4(0.f, 0.f, 0.f, 0.f);
        float  qa_ = 0.f;
        if (j < total) {
            ri = (int)sList[wrp][j];
            int o = b * MAXC + ri;
            qb  = __ldg(&g_nbox[o]);
            qa_ = __ldg(&g_na[o]);
        }
        int nl = total - base; if (nl > 32) nl = 32;
        int keptflag = 0;

        for (int k = 0; k < nl; ++k) {
            float qx1 = __shfl_sync(0xffffffffu, qb.x, k);
            float qy1 = __shfl_sync(0xffffffffu, qb.y, k);
            float qx2 = __shfl_sync(0xffffffffu, qb.z, k);
            float qy2 = __shfl_sync(0xffffffffu, qb.w, k);
            float qa  = __shfl_sync(0xffffffffu, qa_,  k);

            int sup = 0;
            if (lane < nk) {
                float ltx = fmaxf(kx1, qx1);
                float lty = fmaxf(ky1, qy1);
                float rbx = fminf(kx2, qx2);
                float rby = fminf(ky2, qy2);
                float ww  = fmaxf(__fsub_rn(rbx, ltx), 0.0f);
                float hh  = fmaxf(__fsub_rn(rby, lty), 0.0f);
                float inter = __fmul_rn(ww, hh);
                float den = __fadd_rn(__fsub_rn(__fadd_rn(ka, qa), inter), 1e-7f);
                sup = (__fdiv_rn(inter, den) > IOU_T) ? 1 : 0;
            }
            unsigned sb = __ballot_sync(0xffffffffu, sup);
            if (!sb) {
                if (lane == nk) { kx1 = qx1; ky1 = qy1; kx2 = qx2; ky2 = qy2; ka = qa; }
                nk++;
                if (lane == k) keptflag = 1;
            }
        }

        // owning lane writes its output row (outside the dependent chain)
        if (j < total) {
            int o = b * MAXC + ri;
            float* rs = out + (size_t)o * 6;
            if (keptflag) {
                float4 rb = __ldg(&g_rbox[o]);
                rs[0] = rb.x; rs[1] = rb.y; rs[2] = rb.z; rs[3] = rb.w;
                rs[4] = __ldg(&g_conf[o]);
                rs[5] = (float)c;
                out[(size_t)BATCH * MAXC * 6 + o] = 1.0f;
            } else {
                rs[0] = 0.f; rs[1] = 0.f; rs[2] = 0.f;
                rs[3] = 0.f; rs[4] = 0.f; rs[5] = 0.f;
                out[(size_t)BATCH * MAXC * 6 + o] = 0.f;
            }
        }
    }
}

// ---------------- launch ----------------
extern "C" void kernel_launch(void* const* d_in, const int* in_sizes, int n_in,
                              void* d_out, int out_size)
{
    (void)in_sizes; (void)n_in; (void)out_size;
    const float* pred = (const float*)d_in[0];
    float* out = (float*)d_out;

    k_score<<<(BATCH * NANCH) / SAPB, STHREADS>>>(pred);   // 3150 blocks x 512
    k_prep<<<BATCH * PSLICE, 1024>>>();                    // 128 blocks
    k_nms<<<BATCH * (NCLS / CPB), CPB * 32>>>(out);        // 160 blocks
}